// round 15
// baseline (speedup 1.0000x reference)
#include <cuda_runtime.h>
#include <cuda_fp16.h>
#include <math_constants.h>
#include <cstdint>

#define N_TOKENS   16384
#define DIM        2048
#define NEXP       64
#define NCOLS      128
#define NBLK       296
#define BIGB       200               // blocks with 56 tokens; rest have 54
#define ROWS_BIG   56
#define ROWS_SMALL 54
#define NTHREADS   256
#define KC         128
#define NCHUNK     (DIM / KC)        // 16
#define EPS        1e-9f
#define FIX_THR    4e-3f
#define WINDOW     8e-3f

#define PADB       272               // 256B data + 16B pad; 68 banks ≡ 4 mod 32 -> conflict-free ldsm
#define A_TILE     (64 * PADB)       // 17408
#define B_TILE     (128 * PADB)      // 34816
#define A_HI       0
#define B_HI       A_TILE
#define ST_SIZE    (A_TILE + B_TILE) // 52224
#define B_CHUNK_U16X (B_TILE / 16)   // 2176
#define SMEM_BYTES (1024 + 2 * ST_SIZE)   // 105472 -> 2 CTAs/SM

// ---- static device scratch ----
__device__ uint4 g_wpack[NCHUNK * B_CHUNK_U16X];   // 544KB fp16 W
__device__ float g_imp_part [NBLK * NEXP];
__device__ float g_load_part[NBLK * NEXP];
__device__ unsigned int g_ticket;

// ======================= helpers =======================
__device__ __forceinline__ uint32_t smem_u32(const void* p) {
    uint32_t a;
    asm("{ .reg .u64 t; cvta.to.shared.u64 t, %1; cvt.u32.u64 %0, t; }" : "=r"(a) : "l"(p));
    return a;
}
__device__ __forceinline__ void ldsm_x4(uint32_t (&r)[4], uint32_t addr) {
    asm volatile("ldmatrix.sync.aligned.m8n8.x4.shared.b16 {%0,%1,%2,%3}, [%4];"
                 : "=r"(r[0]), "=r"(r[1]), "=r"(r[2]), "=r"(r[3]) : "r"(addr));
}
__device__ __forceinline__ void mma16816h(float* d, const uint32_t* a, uint32_t b0, uint32_t b1) {
    asm volatile("mma.sync.aligned.m16n8k16.row.col.f32.f16.f16.f32 "
                 "{%0,%1,%2,%3}, {%4,%5,%6,%7}, {%8,%9}, {%0,%1,%2,%3};"
                 : "+f"(d[0]), "+f"(d[1]), "+f"(d[2]), "+f"(d[3])
                 : "r"(a[0]), "r"(a[1]), "r"(a[2]), "r"(a[3]), "r"(b0), "r"(b1));
}
#define CP_ASYNC16(dst, src) \
    asm volatile("cp.async.cg.shared.global [%0], [%1], 16;" :: "r"(dst), "l"(src))
#define CP_COMMIT()  asm volatile("cp.async.commit_group;")
#define CP_WAIT0()   asm volatile("cp.async.wait_group 0;")

__device__ __forceinline__ uint4 cvt8h(float4 a, float4 b) {
    __half2 h0 = __floats2half2_rn(a.x, a.y);
    __half2 h1 = __floats2half2_rn(a.z, a.w);
    __half2 h2 = __floats2half2_rn(b.x, b.y);
    __half2 h3 = __floats2half2_rn(b.z, b.w);
    uint4 r;
    r.x = *reinterpret_cast<uint32_t*>(&h0);
    r.y = *reinterpret_cast<uint32_t*>(&h1);
    r.z = *reinterpret_cast<uint32_t*>(&h2);
    r.w = *reinterpret_cast<uint32_t*>(&h3);
    return r;
}

// ======================= W precompute (+ticket reset) =======================
__global__ void __launch_bounds__(256) wpack_kernel(const float* __restrict__ Wg,
                                                    const float* __restrict__ Wn) {
    if (blockIdx.x == 0 && threadIdx.x == 0) g_ticket = 0u;
    int id = blockIdx.x * 256 + threadIdx.x;   // 32768 = 16 chunks * 128 cols * 16 units
    int chunk = id >> 11;
    int rem   = id & 2047;
    int col = rem >> 4, u = rem & 15;
    const float* src = (col < NEXP ? Wg + (size_t)col * DIM : Wn + (size_t)(col - NEXP) * DIM)
                       + chunk * KC + u * 8;
    float4 a = ((const float4*)src)[0];
    float4 b = ((const float4*)src)[1];
    char* base = (char*)g_wpack + (size_t)chunk * B_TILE;
    *(uint4*)(base + col * PADB + u * 16) = cvt8h(a, b);
}

// ======================= main: GEMM + epilogue + fused fixup + finalize =======================
__global__ void __launch_bounds__(NTHREADS, 2)
router_main_kernel(const float* __restrict__ x,
                   const float* __restrict__ noise,
                   const float* __restrict__ Wg,
                   const float* __restrict__ Wn,
                   float* __restrict__ out)
{
    extern __shared__ char sm[];
    const uint32_t smb = smem_u32(sm);
    const uint32_t stb = (smb + 1023u) & ~1023u;
    char* st_ptr = sm + (stb - smb);

    const int tid  = threadIdx.x;
    const int wid  = tid >> 5;           // 0..7
    const int lane = tid & 31;
    const int wm   = wid >> 2;           // 0..1  (32 rows each)
    const int wn   = wid & 3;            // 0..3  (32 cols each)
    const int b    = blockIdx.x;
    const int rows = (b < BIGB) ? ROWS_BIG : ROWS_SMALL;
    const int tok0 = (b < BIGB) ? b * ROWS_BIG : BIGB * ROWS_BIG + (b - BIGB) * ROWS_SMALL;

    // A-stage: 64 rows x 16 units; thread -> row = tid>>2, starting unit = tid&3, 4 units strided by 4
    const int arow = tid >> 2, au0 = tid & 3;
    const bool arow_ok = (arow < rows);

    float acc[2][4][4];
#pragma unroll
    for (int i = 0; i < 2; ++i)
#pragma unroll
        for (int j = 0; j < 4; ++j)
#pragma unroll
            for (int q = 0; q < 4; ++q) acc[i][j][q] = 0.f;

    // ---- prologue ----
    {
        const uint4* src = g_wpack;
        uint32_t d = stb + B_HI;
#pragma unroll
        for (int t = 0; t < 9; ++t) {
            int idx = tid + t * 256;
            if (idx < B_CHUNK_U16X) CP_ASYNC16(d + idx * 16, src + idx);
        }
        CP_COMMIT();

        if (arow_ok) {
            const float* xrow = x + (size_t)(tok0 + arow) * DIM;
            float4 ar[8];
#pragma unroll
            for (int t = 0; t < 4; ++t) {
                const float4* p = (const float4*)(xrow + (au0 + t * 4) * 8);
                ar[2*t]   = p[0];
                ar[2*t+1] = p[1];
            }
#pragma unroll
            for (int t = 0; t < 4; ++t) {
                int u = au0 + t * 4;
                *(uint4*)(st_ptr + A_HI + arow * PADB + u * 16) = cvt8h(ar[2*t], ar[2*t+1]);
            }
        }
        CP_WAIT0();
        __syncthreads();
    }

    const uint32_t a_lane = (uint32_t)((wm * 32 + (lane & 15)) * PADB + (lane >> 4) * 16);
    const uint32_t b_lane = (uint32_t)((wn * 32 + (lane & 15)) * PADB + (lane >> 4) * 16);

    for (int c = 0; c < NCHUNK; ++c) {
        const int buf = c & 1;
        const uint32_t sb = stb + buf * ST_SIZE;
        const bool pf = (c + 1 < NCHUNK);
        char* stn = st_ptr + (buf ^ 1) * ST_SIZE;

        float4 ar[8];
        if (pf) {
            const uint4* src = g_wpack + (size_t)(c + 1) * B_CHUNK_U16X;
            uint32_t d = stb + (buf ^ 1) * ST_SIZE + B_HI;
#pragma unroll
            for (int t = 0; t < 9; ++t) {
                int idx = tid + t * 256;
                if (idx < B_CHUNK_U16X) CP_ASYNC16(d + idx * 16, src + idx);
            }
            CP_COMMIT();
            if (arow_ok) {
                const float* xrow = x + (size_t)(tok0 + arow) * DIM + (c + 1) * KC;
#pragma unroll
                for (int t = 0; t < 4; ++t) {
                    const float4* p = (const float4*)(xrow + (au0 + t * 4) * 8);
                    ar[2*t]   = p[0];
                    ar[2*t+1] = p[1];
                }
            }
        }

#pragma unroll
        for (int ks = 0; ks < 8; ++ks) {
            const uint32_t ko = ks * 32;
            uint32_t ah[2][4];
            ldsm_x4(ah[0], sb + A_HI + a_lane + ko);
            ldsm_x4(ah[1], sb + A_HI + a_lane + 16 * PADB + ko);
            uint32_t bh[2][4];
#pragma unroll
            for (int p = 0; p < 2; ++p)
                ldsm_x4(bh[p], sb + B_HI + b_lane + p * 16 * PADB + ko);
#pragma unroll
            for (int mt = 0; mt < 2; ++mt)
#pragma unroll
                for (int p = 0; p < 2; ++p)
#pragma unroll
                    for (int h = 0; h < 2; ++h)
                        mma16816h(acc[mt][2 * p + h], ah[mt], bh[p][h], bh[p][2 + h]);
        }

        if (pf) {
            if (arow_ok) {
#pragma unroll
                for (int t = 0; t < 4; ++t) {
                    int u = au0 + t * 4;
                    *(uint4*)(stn + A_HI + arow * PADB + u * 16) = cvt8h(ar[2*t], ar[2*t+1]);
                }
            }
            CP_WAIT0();
        }
        __syncthreads();
    }

    // ---------------- epilogue (overlay) ----------------
    float* smf = (float*)st_ptr;
    const int LSTR = 129;
    const int LOGI = 0;                       // [64][129]: 0-63 gate logits, 64-127 noise->sd
    const int V2O  = 64 * 129;                // 8256
    const int V3O  = V2O + 64, W1O = V3O + 64, W2O = W1O + 64;
    const int I1O  = W2O + 64, I2O = I1O + 64;
    const int IMPO = I2O + 64, LDO = IMPO + 256;    // [4][64] each
    const int FLGO = LDO + 256;                     // [64] ints
    const int FIMP = FLGO + 64;                     // [8][64]
    const int FLD2 = FIMP + 512;                    // [8][64]
    const int LIST = FLD2 + 512;                    // [64] ints
    const int NFLG = LIST + 64;

#pragma unroll
    for (int mt = 0; mt < 2; ++mt)
#pragma unroll
        for (int nt = 0; nt < 4; ++nt)
#pragma unroll
            for (int ci = 0; ci < 4; ++ci) {
                int row = wm * 32 + mt * 16 + (lane >> 2) + (ci >> 1) * 8;
                int col = wn * 32 + nt * 8 + (lane & 3) * 2 + (ci & 1);
                smf[LOGI + row * LSTR + col] = acc[mt][nt][ci];
            }
    // zero fixup accumulators
    smf[FIMP + wid * 64 + lane]      = 0.f;
    smf[FIMP + wid * 64 + lane + 32] = 0.f;
    smf[FLD2 + wid * 64 + lane]      = 0.f;
    smf[FLD2 + wid * 64 + lane + 32] = 0.f;
    __syncthreads();

    // E1: approx decision + flag near-ties
    if (tid < rows) {
        const int t = tid;
        const int tg = tok0 + t;
        const float* nrow = noise + (size_t)tg * NEXP;
        float v1 = -CUDART_INF_F, v2 = -CUDART_INF_F, v3 = -CUDART_INF_F;
        int i1 = 0, i2 = 0;
#pragma unroll 4
        for (int e = 0; e < NEXP; ++e) {
            float lg = smf[LOGI + t * LSTR + e];
            float nl = smf[LOGI + t * LSTR + NEXP + e];
            float sp = fmaxf(nl, 0.f) + log1pf(expf(-fabsf(nl)));
            float sd = sp + EPS;
            smf[LOGI + t * LSTR + NEXP + e] = sd;     // overwrite with noise_std
            float nz = fmaf(nrow[e], sd, lg);
            if (nz > v1)      { v3 = v2; v2 = v1; i2 = i1; v1 = nz; i1 = e; }
            else if (nz > v2) { v3 = v2; v2 = nz; i2 = e; }
            else if (nz > v3) { v3 = nz; }
        }
        float ed  = expf(v2 - v1);
        float inv = 1.f / (1.f + ed);
        float w1 = inv, w2 = ed * inv;

        int flag = ((v1 - v2) < FIX_THR) || ((v2 - v3) < FIX_THR);
        out[2 * tg]                    = (float)i1;
        out[2 * tg + 1]                = (float)i2;
        out[2 * N_TOKENS + 2 * tg]     = w1;
        out[2 * N_TOKENS + 2 * tg + 1] = w2;
        out[4 * N_TOKENS + tg]         = w1;
        ((int*)(smf + FLGO))[t] = flag;
        smf[V2O + t] = v2; smf[V3O + t] = v3;
        smf[W1O + t] = w1; smf[W2O + t] = w2;
        ((int*)(smf + I1O))[t] = i1; ((int*)(smf + I2O))[t] = i2;
    }
    __syncthreads();

    // build flagged-token list
    if (tid == 0) {
        int n = 0;
        for (int t = 0; t < rows; ++t)
            if (((int*)(smf + FLGO))[t]) ((int*)(smf + LIST))[n++] = t;
        ((int*)(smf + NFLG))[0] = n;
    }

    // E2: approx partials, skipping flagged (4 groups x 14 tokens)
    {
        const int e = tid & 63, g = tid >> 6;
        float imp = 0.f, ld = 0.f;
        const int tend = min(g * 14 + 14, rows);
        for (int t = g * 14; t < tend; ++t) {
            if (((int*)(smf + FLGO))[t]) continue;
            int ii1 = ((int*)(smf + I1O))[t], ii2 = ((int*)(smf + I2O))[t];
            bool in1 = (ii1 == e), in2 = (ii2 == e);
            if (in1) imp += smf[W1O + t];
            if (in2) imp += smf[W2O + t];
            float kth = (in1 || in2) ? smf[V3O + t] : smf[V2O + t];
            float sd  = smf[LOGI + t * LSTR + NEXP + e];
            float lg  = smf[LOGI + t * LSTR + e];
            float z   = (lg - kth) / (sd + EPS);
            ld += 0.5f * (1.f + erff(z * 0.70710678118654752f));
        }
        smf[IMPO + g * 64 + e] = imp;
        smf[LDO  + g * 64 + e] = ld;
    }
    __syncthreads();

    // ---- fused fixup: warp-per-flagged-token, candidate-only exact dots ----
    const int nflag = ((int*)(smf + NFLG))[0];
    for (int idx = wid; idx < nflag; idx += 8) {
        const int t  = ((int*)(smf + LIST))[idx];
        const int tg = tok0 + t;
        float lga[2], sda[2], nza[2];
#pragma unroll
        for (int j = 0; j < 2; ++j) {
            int e = lane + 32 * j;
            lga[j] = smf[LOGI + t * LSTR + e];
            sda[j] = smf[LOGI + t * LSTR + NEXP + e];
            nza[j] = fmaf(noise[(size_t)tg * NEXP + e], sda[j], lga[j]);
        }
        // approx 3rd max via 3 argmax-exclude passes
        float c0 = nza[0], c1 = nza[1];
        float v3a = -CUDART_INF_F;
#pragma unroll
        for (int pass = 0; pass < 3; ++pass) {
            float m  = fmaxf(c0, c1);
            int  mid = (c0 >= c1) ? (lane * 2) : (lane * 2 + 1);
#pragma unroll
            for (int o = 16; o > 0; o >>= 1) {
                float mv = __shfl_xor_sync(0xFFFFFFFFu, m, o);
                int   mi = __shfl_xor_sync(0xFFFFFFFFu, mid, o);
                if (mv > m || (mv == m && mi < mid)) { m = mv; mid = mi; }
            }
            v3a = m;
            if (mid == lane * 2)     c0 = -CUDART_INF_F;
            if (mid == lane * 2 + 1) c1 = -CUDART_INF_F;
        }
        const float thr = v3a - WINDOW;
        unsigned mask0 = __ballot_sync(0xFFFFFFFFu, nza[0] >= thr);
        unsigned mask1 = __ballot_sync(0xFFFFFFFFu, nza[1] >= thr);

        const float* xr = x + (size_t)tg * DIM;
        float v1x = -CUDART_INF_F, v2x = -CUDART_INF_F, v3x = -CUDART_INF_F;
        int i1 = 0, i2 = 0;

#pragma unroll 1
        for (int half = 0; half < 2; ++half) {
            unsigned m = half ? mask1 : mask0;
            while (m) {
                int e = __ffs(m) - 1 + half * 32;
                m &= m - 1;
                const float* wg = Wg + (size_t)e * DIM;
                const float* wnp = Wn + (size_t)e * DIM;
                float sg = 0.f, sn = 0.f;
#pragma unroll
                for (int jj = 0; jj < 16; ++jj) {
                    int k = lane * 4 + jj * 128;
                    float4 xv = *(const float4*)(xr + k);
                    float4 g4 = *(const float4*)(wg + k);
                    float4 n4 = *(const float4*)(wnp + k);
                    sg = fmaf(xv.x, g4.x, fmaf(xv.y, g4.y, fmaf(xv.z, g4.z, fmaf(xv.w, g4.w, sg))));
                    sn = fmaf(xv.x, n4.x, fmaf(xv.y, n4.y, fmaf(xv.z, n4.z, fmaf(xv.w, n4.w, sn))));
                }
#pragma unroll
                for (int o = 16; o > 0; o >>= 1) {
                    sg += __shfl_xor_sync(0xFFFFFFFFu, sg, o);
                    sn += __shfl_xor_sync(0xFFFFFFFFu, sn, o);
                }
                float sp  = fmaxf(sn, 0.f) + log1pf(expf(-fabsf(sn)));
                float sdx = sp + EPS;
                float nzx = fmaf(noise[(size_t)tg * NEXP + e], sdx, sg);
                if (nzx > v1x)      { v3x = v2x; v2x = v1x; i2 = i1; v1x = nzx; i1 = e; }
                else if (nzx > v2x) { v3x = v2x; v2x = nzx; i2 = e; }
                else if (nzx > v3x) { v3x = nzx; }
            }
        }

        float ed  = expf(v2x - v1x);
        float inv = 1.f / (1.f + ed);
        float w1 = inv, w2 = ed * inv;
        if (lane == 0) {
            out[2 * tg]                    = (float)i1;
            out[2 * tg + 1]                = (float)i2;
            out[2 * N_TOKENS + 2 * tg]     = w1;
            out[2 * N_TOKENS + 2 * tg + 1] = w2;
            out[4 * N_TOKENS + tg]         = w1;
            smf[FIMP + wid * 64 + i1] += w1;
            smf[FIMP + wid * 64 + i2] += w2;
        }
#pragma unroll
        for (int j = 0; j < 2; ++j) {
            int e = lane + 32 * j;
            float kth = (e == i1 || e == i2) ? v3x : v2x;
            float z = (lga[j] - kth) / (sda[j] + EPS);
            smf[FLD2 + wid * 64 + e] += 0.5f * (1.f + erff(z * 0.70710678118654752f));
        }
    }
    __syncthreads();

    // per-block partial store (approx + fixup)
    if (tid < NEXP) {
        float si = 0.f, sl = 0.f;
#pragma unroll
        for (int g = 0; g < 4; ++g) { si += smf[IMPO + g * 64 + tid]; sl += smf[LDO + g * 64 + tid]; }
#pragma unroll
        for (int q = 0; q < 8; ++q) { si += smf[FIMP + q * 64 + tid]; sl += smf[FLD2 + q * 64 + tid]; }
        g_imp_part [b * NEXP + tid] = si;
        g_load_part[b * NEXP + tid] = sl;
    }

    // ---- fused finalize: last block computes aux ----
    __threadfence();
    __shared__ int lastflag;
    if (tid == 0) {
        unsigned tk = atomicAdd(&g_ticket, 1u);
        lastflag = (tk == (unsigned)(NBLK - 1));
    }
    __syncthreads();
    if (!lastflag) return;

    __shared__ float fimp[4][64], fld[4][64];
    {
        const int e = tid & 63, g = tid >> 6;   // 4 groups
        float si = 0.f, sl = 0.f;
        for (int q = g; q < NBLK; q += 4) {
            si += g_imp_part [q * NEXP + e];
            sl += g_load_part[q * NEXP + e];
        }
        fimp[g][e] = si; fld[g][e] = sl;
    }
    __syncthreads();
    __shared__ float timp[64], tld[64];
    if (tid < 64) {
        timp[tid] = fimp[0][tid] + fimp[1][tid] + fimp[2][tid] + fimp[3][tid];
        tld[tid]  = fld[0][tid]  + fld[1][tid]  + fld[2][tid]  + fld[3][tid];
    }
    __syncthreads();
    if (tid < 32) {
        float si = timp[tid] + timp[tid + 32];
        float sl = tld[tid]  + tld[tid + 32];
#pragma unroll
        for (int o = 16; o > 0; o >>= 1) {
            si += __shfl_xor_sync(0xFFFFFFFFu, si, o);
            sl += __shfl_xor_sync(0xFFFFFFFFu, sl, o);
        }
        float mi = si * (1.f / NEXP), ml = sl * (1.f / NEXP);
        float d0 = timp[tid] - mi, d1 = timp[tid + 32] - mi;
        float e0 = tld[tid]  - ml, e1 = tld[tid + 32]  - ml;
        float vi = d0 * d0 + d1 * d1;
        float vl = e0 * e0 + e1 * e1;
#pragma unroll
        for (int o = 16; o > 0; o >>= 1) {
            vi += __shfl_xor_sync(0xFFFFFFFFu, vi, o);
            vl += __shfl_xor_sync(0xFFFFFFFFu, vl, o);
        }
        vi *= (1.f / NEXP); vl *= (1.f / NEXP);
        if (tid == 0)
            out[5 * N_TOKENS] = 0.1f * (vi / (mi * mi + EPS)) + 0.1f * (vl / (ml * ml + EPS));
    }
}

extern "C" void kernel_launch(void* const* d_in, const int* in_sizes, int n_in,
                              void* d_out, int out_size)
{
    const float* x     = (const float*)d_in[0];
    const float* noise = (const float*)d_in[1];
    const float* Wg    = (const float*)d_in[2];
    const float* Wn    = (const float*)d_in[3];
    float* out = (float*)d_out;

    cudaFuncSetAttribute(router_main_kernel,
                         cudaFuncAttributeMaxDynamicSharedMemorySize, SMEM_BYTES);
    wpack_kernel<<<128, 256>>>(Wg, Wn);
    router_main_kernel<<<NBLK, NTHREADS, SMEM_BYTES>>>(x, noise, Wg, Wn, out);
}

// round 16
// speedup vs baseline: 1.0588x; 1.0588x over previous
#include <cuda_runtime.h>
#include <cuda_fp16.h>
#include <math_constants.h>
#include <cstdint>

#define N_TOKENS   16384
#define DIM        2048
#define NEXP       64
#define NCOLS      128
#define NBLK       296
#define NTHREADS   256
#define KC         64
#define NCHUNK     (DIM / KC)        // 32
#define EPS        1e-9f
#define FIX_THR    4e-3f
#define WINDOW     8e-3f

#define PADB       144
#define A_TILE     (64 * PADB)       // 9216
#define B_TILE     (128 * PADB)      // 18432
#define A_HI       0
#define B_HI       A_TILE
#define ST_SIZE    (A_TILE + B_TILE) // 27648
#define B_CHUNK_U16X (B_TILE / 16)   // 1152
#define SMEM_BYTES (1024 + 2 * ST_SIZE)   // 56320 -> 2 CTAs/SM

// ---- static device scratch ----
__device__ uint4 g_wpack[NCHUNK * B_CHUNK_U16X];   // 576KB fp16 W
__device__ float g_imp_part [NBLK * NEXP];
__device__ float g_load_part[NBLK * NEXP];
__device__ unsigned int g_ticket;

// ======================= helpers =======================
__device__ __forceinline__ uint32_t smem_u32(const void* p) {
    uint32_t a;
    asm("{ .reg .u64 t; cvta.to.shared.u64 t, %1; cvt.u32.u64 %0, t; }" : "=r"(a) : "l"(p));
    return a;
}
__device__ __forceinline__ void ldsm_x4(uint32_t (&r)[4], uint32_t addr) {
    asm volatile("ldmatrix.sync.aligned.m8n8.x4.shared.b16 {%0,%1,%2,%3}, [%4];"
                 : "=r"(r[0]), "=r"(r[1]), "=r"(r[2]), "=r"(r[3]) : "r"(addr));
}
__device__ __forceinline__ void mma16816h(float* d, const uint32_t* a, uint32_t b0, uint32_t b1) {
    asm volatile("mma.sync.aligned.m16n8k16.row.col.f32.f16.f16.f32 "
                 "{%0,%1,%2,%3}, {%4,%5,%6,%7}, {%8,%9}, {%0,%1,%2,%3};"
                 : "+f"(d[0]), "+f"(d[1]), "+f"(d[2]), "+f"(d[3])
                 : "r"(a[0]), "r"(a[1]), "r"(a[2]), "r"(a[3]), "r"(b0), "r"(b1));
}
#define CP_ASYNC16(dst, src) \
    asm volatile("cp.async.cg.shared.global [%0], [%1], 16;" :: "r"(dst), "l"(src))
#define CP_COMMIT()  asm volatile("cp.async.commit_group;")
#define CP_WAIT0()   asm volatile("cp.async.wait_group 0;")

__device__ __forceinline__ uint4 cvt8h(float4 a, float4 b) {
    __half2 h0 = __floats2half2_rn(a.x, a.y);
    __half2 h1 = __floats2half2_rn(a.z, a.w);
    __half2 h2 = __floats2half2_rn(b.x, b.y);
    __half2 h3 = __floats2half2_rn(b.z, b.w);
    uint4 r;
    r.x = *reinterpret_cast<uint32_t*>(&h0);
    r.y = *reinterpret_cast<uint32_t*>(&h1);
    r.z = *reinterpret_cast<uint32_t*>(&h2);
    r.w = *reinterpret_cast<uint32_t*>(&h3);
    return r;
}

// ======================= W precompute (+ticket reset) =======================
__global__ void __launch_bounds__(256) wpack_kernel(const float* __restrict__ Wg,
                                                    const float* __restrict__ Wn) {
    if (blockIdx.x == 0 && threadIdx.x == 0) g_ticket = 0u;
    int id = blockIdx.x * 256 + threadIdx.x;
    int chunk = id >> 10;
    int rem   = id & 1023;
    int col = rem >> 3, u = rem & 7;
    const float* src = (col < NEXP ? Wg + (size_t)col * DIM : Wn + (size_t)(col - NEXP) * DIM)
                       + chunk * KC + u * 8;
    float4 a = ((const float4*)src)[0];
    float4 b = ((const float4*)src)[1];
    char* base = (char*)g_wpack + (size_t)chunk * B_TILE;
    *(uint4*)(base + col * PADB + u * 16) = cvt8h(a, b);
}

// ======================= main: GEMM + epilogue + fused fixup + finalize =======================
__global__ void __launch_bounds__(NTHREADS, 2)
router_main_kernel(const float* __restrict__ x,
                   const float* __restrict__ noise,
                   const float* __restrict__ Wg,
                   const float* __restrict__ Wn,
                   float* __restrict__ out)
{
    extern __shared__ char sm[];
    const uint32_t smb = smem_u32(sm);
    const uint32_t stb = (smb + 1023u) & ~1023u;
    char* st_ptr = sm + (stb - smb);

    const int tid  = threadIdx.x;
    const int wid  = tid >> 5;           // 0..7
    const int lane = tid & 31;
    const int wm   = wid >> 2;           // 0..1  (32 rows each)
    const int wn   = wid & 3;            // 0..3  (32 cols each)
    const int b    = blockIdx.x;

    // zero-waste tiling: big blocks (64 rows) at b<68 and b>=228, small (48) in between.
    // bid and bid+148 co-reside on one SM -> most SMs get 64+48=112 rows.
    int rows, tok0;
    if (b < 68)       { rows = 64; tok0 = b * 64; }
    else if (b < 228) { rows = 48; tok0 = 4352 + (b - 68) * 48; }
    else              { rows = 64; tok0 = 12032 + (b - 228) * 64; }

    const int arow = tid >> 3, au = tid & 7;        // A-stage: idx = tid + t*256
    const bool mt1 = (rows - wm * 32) >= 32;        // does this warp own a 2nd 16-row tile?

    float acc[2][4][4];
#pragma unroll
    for (int i = 0; i < 2; ++i)
#pragma unroll
        for (int j = 0; j < 4; ++j)
#pragma unroll
            for (int q = 0; q < 4; ++q) acc[i][j][q] = 0.f;

    // ---- prologue ----
    {
        const uint4* src = g_wpack;
        uint32_t d = stb + B_HI;
#pragma unroll
        for (int t = 0; t < 5; ++t) {
            int idx = tid + t * 256;
            if (idx < B_CHUNK_U16X) CP_ASYNC16(d + idx * 16, src + idx);
        }
        CP_COMMIT();

#pragma unroll
        for (int t = 0; t < 2; ++t) {
            int r = arow + t * 32;
            if (r < rows) {
                const float4* p = (const float4*)(x + (size_t)(tok0 + r) * DIM + au * 8);
                *(uint4*)(st_ptr + A_HI + r * PADB + au * 16) = cvt8h(p[0], p[1]);
            }
        }
        CP_WAIT0();
        __syncthreads();
    }

    const uint32_t a_lane = (uint32_t)((wm * 32 + (lane & 15)) * PADB + (lane >> 4) * 16);
    const uint32_t b_lane = (uint32_t)((wn * 32 + (lane & 15)) * PADB + (lane >> 4) * 16);

    for (int c = 0; c < NCHUNK; ++c) {
        const int buf = c & 1;
        const uint32_t sb = stb + buf * ST_SIZE;
        const bool pf = (c + 1 < NCHUNK);
        char* stn = st_ptr + (buf ^ 1) * ST_SIZE;

        float4 ar[4];
        bool aload[2] = {false, false};
        if (pf) {
            const uint4* src = g_wpack + (size_t)(c + 1) * B_CHUNK_U16X;
            uint32_t d = stb + (buf ^ 1) * ST_SIZE + B_HI;
#pragma unroll
            for (int t = 0; t < 5; ++t) {
                int idx = tid + t * 256;
                if (idx < B_CHUNK_U16X) CP_ASYNC16(d + idx * 16, src + idx);
            }
            CP_COMMIT();
            const int koff = (c + 1) * KC;
#pragma unroll
            for (int t = 0; t < 2; ++t) {
                int r = arow + t * 32;
                if (r < rows) {
                    aload[t] = true;
                    const float4* p = (const float4*)(x + (size_t)(tok0 + r) * DIM + koff + au * 8);
                    ar[2*t]   = p[0];
                    ar[2*t+1] = p[1];
                }
            }
        }

#pragma unroll
        for (int ks = 0; ks < 4; ++ks) {
            const uint32_t ko = ks * 32;
            uint32_t ah[2][4];
            ldsm_x4(ah[0], sb + A_HI + a_lane + ko);
            if (mt1) ldsm_x4(ah[1], sb + A_HI + a_lane + 16 * PADB + ko);
            uint32_t bh[2][4];
#pragma unroll
            for (int p = 0; p < 2; ++p)
                ldsm_x4(bh[p], sb + B_HI + b_lane + p * 16 * PADB + ko);
#pragma unroll
            for (int p = 0; p < 2; ++p)
#pragma unroll
                for (int h = 0; h < 2; ++h)
                    mma16816h(acc[0][2 * p + h], ah[0], bh[p][h], bh[p][2 + h]);
            if (mt1) {
#pragma unroll
                for (int p = 0; p < 2; ++p)
#pragma unroll
                    for (int h = 0; h < 2; ++h)
                        mma16816h(acc[1][2 * p + h], ah[1], bh[p][h], bh[p][2 + h]);
            }
        }

        if (pf) {
#pragma unroll
            for (int t = 0; t < 2; ++t) {
                if (aload[t]) {
                    int r = arow + t * 32;
                    *(uint4*)(stn + A_HI + r * PADB + au * 16) = cvt8h(ar[2*t], ar[2*t+1]);
                }
            }
            CP_WAIT0();
        }
        __syncthreads();
    }

    // ---------------- epilogue (overlay) ----------------
    float* smf = (float*)st_ptr;
    const int LSTR = 129;
    const int LOGI = 0;                       // [64][129]: 0-63 gate logits, 64-127 noise->sd
    const int V2O  = 64 * 129;                // 8256
    const int V3O  = V2O + 64, W1O = V3O + 64, W2O = W1O + 64;
    const int I1O  = W2O + 64, I2O = I1O + 64;
    const int IMPO = I2O + 64, LDO = IMPO + 256;    // [4][64] each
    const int FLGO = LDO + 256;                     // [64] ints
    const int FIMP = FLGO + 64;                     // [8][64]
    const int FLD2 = FIMP + 512;                    // [8][64]
    const int LIST = FLD2 + 512;                    // [64] ints
    const int NFLG = LIST + 64;

#pragma unroll
    for (int mt = 0; mt < 2; ++mt)
#pragma unroll
        for (int nt = 0; nt < 4; ++nt)
#pragma unroll
            for (int ci = 0; ci < 4; ++ci) {
                int row = wm * 32 + mt * 16 + (lane >> 2) + (ci >> 1) * 8;
                int col = wn * 32 + nt * 8 + (lane & 3) * 2 + (ci & 1);
                smf[LOGI + row * LSTR + col] = acc[mt][nt][ci];
            }
    // zero fixup accumulators
    smf[FIMP + wid * 64 + lane]      = 0.f;
    smf[FIMP + wid * 64 + lane + 32] = 0.f;
    smf[FLD2 + wid * 64 + lane]      = 0.f;
    smf[FLD2 + wid * 64 + lane + 32] = 0.f;
    __syncthreads();

    // E1: approx decision + flag near-ties
    if (tid < rows) {
        const int t = tid;
        const int tg = tok0 + t;
        const float* nrow = noise + (size_t)tg * NEXP;
        float v1 = -CUDART_INF_F, v2 = -CUDART_INF_F, v3 = -CUDART_INF_F;
        int i1 = 0, i2 = 0;
#pragma unroll 4
        for (int e = 0; e < NEXP; ++e) {
            float lg = smf[LOGI + t * LSTR + e];
            float nl = smf[LOGI + t * LSTR + NEXP + e];
            float sp = fmaxf(nl, 0.f) + log1pf(expf(-fabsf(nl)));
            float sd = sp + EPS;
            smf[LOGI + t * LSTR + NEXP + e] = sd;     // overwrite with noise_std
            float nz = fmaf(nrow[e], sd, lg);
            if (nz > v1)      { v3 = v2; v2 = v1; i2 = i1; v1 = nz; i1 = e; }
            else if (nz > v2) { v3 = v2; v2 = nz; i2 = e; }
            else if (nz > v3) { v3 = nz; }
        }
        float ed  = expf(v2 - v1);
        float inv = 1.f / (1.f + ed);
        float w1 = inv, w2 = ed * inv;

        int flag = ((v1 - v2) < FIX_THR) || ((v2 - v3) < FIX_THR);
        out[2 * tg]                    = (float)i1;
        out[2 * tg + 1]                = (float)i2;
        out[2 * N_TOKENS + 2 * tg]     = w1;
        out[2 * N_TOKENS + 2 * tg + 1] = w2;
        out[4 * N_TOKENS + tg]         = w1;
        ((int*)(smf + FLGO))[t] = flag;
        smf[V2O + t] = v2; smf[V3O + t] = v3;
        smf[W1O + t] = w1; smf[W2O + t] = w2;
        ((int*)(smf + I1O))[t] = i1; ((int*)(smf + I2O))[t] = i2;
    }
    __syncthreads();

    // build flagged-token list
    if (tid == 0) {
        int n = 0;
        for (int t = 0; t < rows; ++t)
            if (((int*)(smf + FLGO))[t]) ((int*)(smf + LIST))[n++] = t;
        ((int*)(smf + NFLG))[0] = n;
    }

    // E2: approx partials, skipping flagged (4 groups x 16 tokens)
    {
        const int e = tid & 63, g = tid >> 6;
        float imp = 0.f, ld = 0.f;
        const int tend = min(g * 16 + 16, rows);
        for (int t = g * 16; t < tend; ++t) {
            if (((int*)(smf + FLGO))[t]) continue;
            int ii1 = ((int*)(smf + I1O))[t], ii2 = ((int*)(smf + I2O))[t];
            bool in1 = (ii1 == e), in2 = (ii2 == e);
            if (in1) imp += smf[W1O + t];
            if (in2) imp += smf[W2O + t];
            float kth = (in1 || in2) ? smf[V3O + t] : smf[V2O + t];
            float sd  = smf[LOGI + t * LSTR + NEXP + e];
            float lg  = smf[LOGI + t * LSTR + e];
            float z   = (lg - kth) / (sd + EPS);
            ld += 0.5f * (1.f + erff(z * 0.70710678118654752f));
        }
        smf[IMPO + g * 64 + e] = imp;
        smf[LDO  + g * 64 + e] = ld;
    }
    __syncthreads();

    // ---- fused fixup: warp-per-flagged-token, candidate-only exact dots ----
    const int nflag = ((int*)(smf + NFLG))[0];
    for (int idx = wid; idx < nflag; idx += 8) {
        const int t  = ((int*)(smf + LIST))[idx];
        const int tg = tok0 + t;
        float lga[2], sda[2], nza[2];
#pragma unroll
        for (int j = 0; j < 2; ++j) {
            int e = lane + 32 * j;
            lga[j] = smf[LOGI + t * LSTR + e];
            sda[j] = smf[LOGI + t * LSTR + NEXP + e];
            nza[j] = fmaf(noise[(size_t)tg * NEXP + e], sda[j], lga[j]);
        }
        // approx 3rd max via 3 argmax-exclude passes
        float c0 = nza[0], c1 = nza[1];
        float v3a = -CUDART_INF_F;
#pragma unroll
        for (int pass = 0; pass < 3; ++pass) {
            float m  = fmaxf(c0, c1);
            int  mid = (c0 >= c1) ? (lane * 2) : (lane * 2 + 1);
#pragma unroll
            for (int o = 16; o > 0; o >>= 1) {
                float mv = __shfl_xor_sync(0xFFFFFFFFu, m, o);
                int   mi = __shfl_xor_sync(0xFFFFFFFFu, mid, o);
                if (mv > m || (mv == m && mi < mid)) { m = mv; mid = mi; }
            }
            v3a = m;
            if (mid == lane * 2)     c0 = -CUDART_INF_F;
            if (mid == lane * 2 + 1) c1 = -CUDART_INF_F;
        }
        const float thr = v3a - WINDOW;
        unsigned mask0 = __ballot_sync(0xFFFFFFFFu, nza[0] >= thr);
        unsigned mask1 = __ballot_sync(0xFFFFFFFFu, nza[1] >= thr);

        const float* xr = x + (size_t)tg * DIM;
        float v1x = -CUDART_INF_F, v2x = -CUDART_INF_F, v3x = -CUDART_INF_F;
        int i1 = 0, i2 = 0;

#pragma unroll 1
        for (int half = 0; half < 2; ++half) {
            unsigned m = half ? mask1 : mask0;
            while (m) {
                int e = __ffs(m) - 1 + half * 32;
                m &= m - 1;
                const float* wg = Wg + (size_t)e * DIM;
                const float* wnp = Wn + (size_t)e * DIM;
                float sg = 0.f, sn = 0.f;
#pragma unroll
                for (int jj = 0; jj < 16; ++jj) {
                    int k = lane * 4 + jj * 128;
                    float4 xv = *(const float4*)(xr + k);
                    float4 g4 = *(const float4*)(wg + k);
                    float4 n4 = *(const float4*)(wnp + k);
                    sg = fmaf(xv.x, g4.x, fmaf(xv.y, g4.y, fmaf(xv.z, g4.z, fmaf(xv.w, g4.w, sg))));
                    sn = fmaf(xv.x, n4.x, fmaf(xv.y, n4.y, fmaf(xv.z, n4.z, fmaf(xv.w, n4.w, sn))));
                }
#pragma unroll
                for (int o = 16; o > 0; o >>= 1) {
                    sg += __shfl_xor_sync(0xFFFFFFFFu, sg, o);
                    sn += __shfl_xor_sync(0xFFFFFFFFu, sn, o);
                }
                float sp  = fmaxf(sn, 0.f) + log1pf(expf(-fabsf(sn)));
                float sdx = sp + EPS;
                float nzx = fmaf(noise[(size_t)tg * NEXP + e], sdx, sg);
                if (nzx > v1x)      { v3x = v2x; v2x = v1x; i2 = i1; v1x = nzx; i1 = e; }
                else if (nzx > v2x) { v3x = v2x; v2x = nzx; i2 = e; }
                else if (nzx > v3x) { v3x = nzx; }
            }
        }

        float ed  = expf(v2x - v1x);
        float inv = 1.f / (1.f + ed);
        float w1 = inv, w2 = ed * inv;
        if (lane == 0) {
            out[2 * tg]                    = (float)i1;
            out[2 * tg + 1]                = (float)i2;
            out[2 * N_TOKENS + 2 * tg]     = w1;
            out[2 * N_TOKENS + 2 * tg + 1] = w2;
            out[4 * N_TOKENS + tg]         = w1;
            smf[FIMP + wid * 64 + i1] += w1;
            smf[FIMP + wid * 64 + i2] += w2;
        }
#pragma unroll
        for (int j = 0; j < 2; ++j) {
            int e = lane + 32 * j;
            float kth = (e == i1 || e == i2) ? v3x : v2x;
            float z = (lga[j] - kth) / (sda[j] + EPS);
            smf[FLD2 + wid * 64 + e] += 0.5f * (1.f + erff(z * 0.70710678118654752f));
        }
    }
    __syncthreads();

    // per-block partial store (approx + fixup)
    if (tid < NEXP) {
        float si = 0.f, sl = 0.f;
#pragma unroll
        for (int g = 0; g < 4; ++g) { si += smf[IMPO + g * 64 + tid]; sl += smf[LDO + g * 64 + tid]; }
#pragma unroll
        for (int q = 0; q < 8; ++q) { si += smf[FIMP + q * 64 + tid]; sl += smf[FLD2 + q * 64 + tid]; }
        g_imp_part [b * NEXP + tid] = si;
        g_load_part[b * NEXP + tid] = sl;
    }

    // ---- fused finalize: last block computes aux ----
    __threadfence();
    __shared__ int lastflag;
    if (tid == 0) {
        unsigned tk = atomicAdd(&g_ticket, 1u);
        lastflag = (tk == (unsigned)(NBLK - 1));
    }
    __syncthreads();
    if (!lastflag) return;

    __shared__ float fimp[4][64], fld[4][64];
    {
        const int e = tid & 63, g = tid >> 6;   // 4 groups
        float si = 0.f, sl = 0.f;
        for (int q = g; q < NBLK; q += 4) {
            si += g_imp_part [q * NEXP + e];
            sl += g_load_part[q * NEXP + e];
        }
        fimp[g][e] = si; fld[g][e] = sl;
    }
    __syncthreads();
    __shared__ float timp[64], tld[64];
    if (tid < 64) {
        timp[tid] = fimp[0][tid] + fimp[1][tid] + fimp[2][tid] + fimp[3][tid];
        tld[tid]  = fld[0][tid]  + fld[1][tid]  + fld[2][tid]  + fld[3][tid];
    }
    __syncthreads();
    if (tid < 32) {
        float si = timp[tid] + timp[tid + 32];
        float sl = tld[tid]  + tld[tid + 32];
#pragma unroll
        for (int o = 16; o > 0; o >>= 1) {
            si += __shfl_xor_sync(0xFFFFFFFFu, si, o);
            sl += __shfl_xor_sync(0xFFFFFFFFu, sl, o);
        }
        float mi = si * (1.f / NEXP), ml = sl * (1.f / NEXP);
        float d0 = timp[tid] - mi, d1 = timp[tid + 32] - mi;
        float e0 = tld[tid]  - ml, e1 = tld[tid + 32]  - ml;
        float vi = d0 * d0 + d1 * d1;
        float vl = e0 * e0 + e1 * e1;
#pragma unroll
        for (int o = 16; o > 0; o >>= 1) {
            vi += __shfl_xor_sync(0xFFFFFFFFu, vi, o);
            vl += __shfl_xor_sync(0xFFFFFFFFu, vl, o);
        }
        vi *= (1.f / NEXP); vl *= (1.f / NEXP);
        if (tid == 0)
            out[5 * N_TOKENS] = 0.1f * (vi / (mi * mi + EPS)) + 0.1f * (vl / (ml * ml + EPS));
    }
}

extern "C" void kernel_launch(void* const* d_in, const int* in_sizes, int n_in,
                              void* d_out, int out_size)
{
    const float* x     = (const float*)d_in[0];
    const float* noise = (const float*)d_in[1];
    const float* Wg    = (const float*)d_in[2];
    const float* Wn    = (const float*)d_in[3];
    float* out = (float*)d_out;

    cudaFuncSetAttribute(router_main_kernel,
                         cudaFuncAttributeMaxDynamicSharedMemorySize, SMEM_BYTES);
    wpack_kernel<<<128, 256>>>(Wg, Wn);
    router_main_kernel<<<NBLK, NTHREADS, SMEM_BYTES>>>(x, noise, Wg, Wn, out);
}

// round 17
// speedup vs baseline: 1.0867x; 1.0264x over previous
#include <cuda_runtime.h>
#include <cuda_fp16.h>
#include <math_constants.h>
#include <cstdint>

#define N_TOKENS   16384
#define DIM        2048
#define NEXP       64
#define NCOLS      128
#define NBLK       296
#define BIGB       200               // blocks with 56 tokens; rest have 54
#define ROWS_BIG   56
#define ROWS_SMALL 54
#define NTHREADS   256
#define KC         64
#define NCHUNK     (DIM / KC)        // 32
#define EPS        1e-9f
#define FIX_THR    4e-3f
#define WINDOW     8e-3f

#define PADB       144
#define A_TILE     (64 * PADB)       // 9216
#define B_TILE     (128 * PADB)      // 18432
#define A_HI       0
#define B_HI       A_TILE
#define ST_SIZE    (A_TILE + B_TILE) // 27648
#define NSTAGE     3
#define B_CHUNK_U16X (B_TILE / 16)   // 1152
#define SMEM_BYTES (1024 + NSTAGE * ST_SIZE)   // 83968 -> 2 CTAs/SM

// ---- static device scratch ----
__device__ uint4 g_wpack[NCHUNK * B_CHUNK_U16X];   // 576KB fp16 W
__device__ float g_imp_part [NBLK * NEXP];
__device__ float g_load_part[NBLK * NEXP];
__device__ unsigned int g_ticket;

// ======================= helpers =======================
__device__ __forceinline__ uint32_t smem_u32(const void* p) {
    uint32_t a;
    asm("{ .reg .u64 t; cvta.to.shared.u64 t, %1; cvt.u32.u64 %0, t; }" : "=r"(a) : "l"(p));
    return a;
}
__device__ __forceinline__ void ldsm_x4(uint32_t (&r)[4], uint32_t addr) {
    asm volatile("ldmatrix.sync.aligned.m8n8.x4.shared.b16 {%0,%1,%2,%3}, [%4];"
                 : "=r"(r[0]), "=r"(r[1]), "=r"(r[2]), "=r"(r[3]) : "r"(addr));
}
__device__ __forceinline__ void mma16816h(float* d, const uint32_t* a, uint32_t b0, uint32_t b1) {
    asm volatile("mma.sync.aligned.m16n8k16.row.col.f32.f16.f16.f32 "
                 "{%0,%1,%2,%3}, {%4,%5,%6,%7}, {%8,%9}, {%0,%1,%2,%3};"
                 : "+f"(d[0]), "+f"(d[1]), "+f"(d[2]), "+f"(d[3])
                 : "r"(a[0]), "r"(a[1]), "r"(a[2]), "r"(a[3]), "r"(b0), "r"(b1));
}
#define CP_ASYNC16(dst, src) \
    asm volatile("cp.async.cg.shared.global [%0], [%1], 16;" :: "r"(dst), "l"(src))
#define CP_COMMIT()  asm volatile("cp.async.commit_group;")
#define CP_WAIT0()   asm volatile("cp.async.wait_group 0;")
#define CP_WAIT1()   asm volatile("cp.async.wait_group 1;")

__device__ __forceinline__ uint4 cvt8h(float4 a, float4 b) {
    __half2 h0 = __floats2half2_rn(a.x, a.y);
    __half2 h1 = __floats2half2_rn(a.z, a.w);
    __half2 h2 = __floats2half2_rn(b.x, b.y);
    __half2 h3 = __floats2half2_rn(b.z, b.w);
    uint4 r;
    r.x = *reinterpret_cast<uint32_t*>(&h0);
    r.y = *reinterpret_cast<uint32_t*>(&h1);
    r.z = *reinterpret_cast<uint32_t*>(&h2);
    r.w = *reinterpret_cast<uint32_t*>(&h3);
    return r;
}

// ======================= W precompute (+ticket reset) =======================
__global__ void __launch_bounds__(256) wpack_kernel(const float* __restrict__ Wg,
                                                    const float* __restrict__ Wn) {
    if (blockIdx.x == 0 && threadIdx.x == 0) g_ticket = 0u;
    int id = blockIdx.x * 256 + threadIdx.x;
    int chunk = id >> 10;
    int rem   = id & 1023;
    int col = rem >> 3, u = rem & 7;
    const float* src = (col < NEXP ? Wg + (size_t)col * DIM : Wn + (size_t)(col - NEXP) * DIM)
                       + chunk * KC + u * 8;
    float4 a = ((const float4*)src)[0];
    float4 b = ((const float4*)src)[1];
    char* base = (char*)g_wpack + (size_t)chunk * B_TILE;
    *(uint4*)(base + col * PADB + u * 16) = cvt8h(a, b);
}

// ======================= main: GEMM + epilogue + fused fixup + finalize =======================
__global__ void __launch_bounds__(NTHREADS, 2)
router_main_kernel(const float* __restrict__ x,
                   const float* __restrict__ noise,
                   const float* __restrict__ Wg,
                   const float* __restrict__ Wn,
                   float* __restrict__ out)
{
    extern __shared__ char sm[];
    const uint32_t smb = smem_u32(sm);
    const uint32_t stb = (smb + 1023u) & ~1023u;
    char* st_ptr = sm + (stb - smb);

    const int tid  = threadIdx.x;
    const int wid  = tid >> 5;           // 0..7
    const int lane = tid & 31;
    const int wm   = wid >> 2;           // 0..1  (32 rows each)
    const int wn   = wid & 3;            // 0..3  (32 cols each)
    const int b    = blockIdx.x;
    const int rows = (b < BIGB) ? ROWS_BIG : ROWS_SMALL;
    const int tok0 = (b < BIGB) ? b * ROWS_BIG : BIGB * ROWS_BIG + (b - BIGB) * ROWS_SMALL;

    const int arow = tid >> 3, au = tid & 7;        // A-stage: idx = tid + t*256 (64 rows x 8 units)

    float acc[2][4][4];
#pragma unroll
    for (int i = 0; i < 2; ++i)
#pragma unroll
        for (int j = 0; j < 4; ++j)
#pragma unroll
            for (int q = 0; q < 4; ++q) acc[i][j][q] = 0.f;

    // ---- prologue: B(0) -> stage0 (G0), B(1) -> stage1 (G1), A(0) -> stage0 ----
    {
#pragma unroll
        for (int t = 0; t < 5; ++t) {
            int idx = tid + t * 256;
            if (idx < B_CHUNK_U16X)
                CP_ASYNC16(stb + 0 * ST_SIZE + B_HI + idx * 16, g_wpack + idx);
        }
        CP_COMMIT();
#pragma unroll
        for (int t = 0; t < 5; ++t) {
            int idx = tid + t * 256;
            if (idx < B_CHUNK_U16X)
                CP_ASYNC16(stb + 1 * ST_SIZE + B_HI + idx * 16, g_wpack + B_CHUNK_U16X + idx);
        }
        CP_COMMIT();

#pragma unroll
        for (int t = 0; t < 2; ++t) {
            int r = arow + t * 32;
            if (r < rows) {
                const float4* p = (const float4*)(x + (size_t)(tok0 + r) * DIM + au * 8);
                *(uint4*)(st_ptr + A_HI + r * PADB + au * 16) = cvt8h(p[0], p[1]);
            }
        }
        CP_WAIT1();          // G0 complete; G1 still in flight
        __syncthreads();
    }

    const uint32_t a_lane = (uint32_t)((wm * 32 + (lane & 15)) * PADB + (lane >> 4) * 16);
    const uint32_t b_lane = (uint32_t)((wn * 32 + (lane & 15)) * PADB + (lane >> 4) * 16);

    int buf = 0;
    for (int c = 0; c < NCHUNK; ++c) {
        const uint32_t sb = stb + buf * ST_SIZE;
        int bufn = buf + 1; if (bufn == NSTAGE) bufn = 0;
        int buf2 = bufn + 1; if (buf2 == NSTAGE) buf2 = 0;

        // issue B(c+2) into stage (c+2)%3
        if (c + 2 < NCHUNK) {
            const uint4* src = g_wpack + (size_t)(c + 2) * B_CHUNK_U16X;
            uint32_t d = stb + buf2 * ST_SIZE + B_HI;
#pragma unroll
            for (int t = 0; t < 5; ++t) {
                int idx = tid + t * 256;
                if (idx < B_CHUNK_U16X) CP_ASYNC16(d + idx * 16, src + idx);
            }
            CP_COMMIT();
        }

        // LDG A(c+1) into regs
        float4 ar[4];
        bool aload[2] = {false, false};
        if (c + 1 < NCHUNK) {
            const int koff = (c + 1) * KC;
#pragma unroll
            for (int t = 0; t < 2; ++t) {
                int r = arow + t * 32;
                if (r < rows) {
                    aload[t] = true;
                    const float4* p = (const float4*)(x + (size_t)(tok0 + r) * DIM + koff + au * 8);
                    ar[2*t]   = p[0];
                    ar[2*t+1] = p[1];
                }
            }
        }

        // MMA over chunk c
#pragma unroll
        for (int ks = 0; ks < 4; ++ks) {
            const uint32_t ko = ks * 32;
            uint32_t ah[2][4];
            ldsm_x4(ah[0], sb + A_HI + a_lane + ko);
            ldsm_x4(ah[1], sb + A_HI + a_lane + 16 * PADB + ko);
            uint32_t bh[2][4];
#pragma unroll
            for (int p = 0; p < 2; ++p)
                ldsm_x4(bh[p], sb + B_HI + b_lane + p * 16 * PADB + ko);
#pragma unroll
            for (int mt = 0; mt < 2; ++mt)
#pragma unroll
                for (int p = 0; p < 2; ++p)
#pragma unroll
                    for (int h = 0; h < 2; ++h)
                        mma16816h(acc[mt][2 * p + h], ah[mt], bh[p][h], bh[p][2 + h]);
        }

        // store A(c+1) into stage (c+1)%3
        if (c + 1 < NCHUNK) {
            char* stn = st_ptr + bufn * ST_SIZE;
#pragma unroll
            for (int t = 0; t < 2; ++t) {
                if (aload[t]) {
                    int r = arow + t * 32;
                    *(uint4*)(stn + A_HI + r * PADB + au * 16) = cvt8h(ar[2*t], ar[2*t+1]);
                }
            }
        }

        // ensure B(c+1) complete before next iteration consumes stage (c+1)%3
        if (c + 2 < NCHUNK)      CP_WAIT1();
        else if (c + 1 < NCHUNK) CP_WAIT0();
        __syncthreads();
        buf = bufn;
    }

    // ---------------- epilogue (overlay) ----------------
    float* smf = (float*)st_ptr;
    const int LSTR = 129;
    const int LOGI = 0;                       // [64][129]: 0-63 gate logits, 64-127 noise->sd
    const int V2O  = 64 * 129;                // 8256
    const int V3O  = V2O + 64, W1O = V3O + 64, W2O = W1O + 64;
    const int I1O  = W2O + 64, I2O = I1O + 64;
    const int IMPO = I2O + 64, LDO = IMPO + 256;    // [4][64] each
    const int FLGO = LDO + 256;                     // [64] ints
    const int FIMP = FLGO + 64;                     // [8][64]
    const int FLD2 = FIMP + 512;                    // [8][64]
    const int LIST = FLD2 + 512;                    // [64] ints
    const int NFLG = LIST + 64;

#pragma unroll
    for (int mt = 0; mt < 2; ++mt)
#pragma unroll
        for (int nt = 0; nt < 4; ++nt)
#pragma unroll
            for (int ci = 0; ci < 4; ++ci) {
                int row = wm * 32 + mt * 16 + (lane >> 2) + (ci >> 1) * 8;
                int col = wn * 32 + nt * 8 + (lane & 3) * 2 + (ci & 1);
                smf[LOGI + row * LSTR + col] = acc[mt][nt][ci];
            }
    // zero fixup accumulators
    smf[FIMP + wid * 64 + lane]      = 0.f;
    smf[FIMP + wid * 64 + lane + 32] = 0.f;
    smf[FLD2 + wid * 64 + lane]      = 0.f;
    smf[FLD2 + wid * 64 + lane + 32] = 0.f;
    __syncthreads();

    // E1: approx decision + flag near-ties
    if (tid < rows) {
        const int t = tid;
        const int tg = tok0 + t;
        const float* nrow = noise + (size_t)tg * NEXP;
        float v1 = -CUDART_INF_F, v2 = -CUDART_INF_F, v3 = -CUDART_INF_F;
        int i1 = 0, i2 = 0;
#pragma unroll 4
        for (int e = 0; e < NEXP; ++e) {
            float lg = smf[LOGI + t * LSTR + e];
            float nl = smf[LOGI + t * LSTR + NEXP + e];
            float sp = fmaxf(nl, 0.f) + log1pf(expf(-fabsf(nl)));
            float sd = sp + EPS;
            smf[LOGI + t * LSTR + NEXP + e] = sd;     // overwrite with noise_std
            float nz = fmaf(nrow[e], sd, lg);
            if (nz > v1)      { v3 = v2; v2 = v1; i2 = i1; v1 = nz; i1 = e; }
            else if (nz > v2) { v3 = v2; v2 = nz; i2 = e; }
            else if (nz > v3) { v3 = nz; }
        }
        float ed  = expf(v2 - v1);
        float inv = 1.f / (1.f + ed);
        float w1 = inv, w2 = ed * inv;

        int flag = ((v1 - v2) < FIX_THR) || ((v2 - v3) < FIX_THR);
        out[2 * tg]                    = (float)i1;
        out[2 * tg + 1]                = (float)i2;
        out[2 * N_TOKENS + 2 * tg]     = w1;
        out[2 * N_TOKENS + 2 * tg + 1] = w2;
        out[4 * N_TOKENS + tg]         = w1;
        ((int*)(smf + FLGO))[t] = flag;
        smf[V2O + t] = v2; smf[V3O + t] = v3;
        smf[W1O + t] = w1; smf[W2O + t] = w2;
        ((int*)(smf + I1O))[t] = i1; ((int*)(smf + I2O))[t] = i2;
    }
    __syncthreads();

    // build flagged-token list
    if (tid == 0) {
        int n = 0;
        for (int t = 0; t < rows; ++t)
            if (((int*)(smf + FLGO))[t]) ((int*)(smf + LIST))[n++] = t;
        ((int*)(smf + NFLG))[0] = n;
    }

    // E2: approx partials, skipping flagged (4 groups x 14 tokens)
    {
        const int e = tid & 63, g = tid >> 6;
        float imp = 0.f, ld = 0.f;
        const int tend = min(g * 14 + 14, rows);
        for (int t = g * 14; t < tend; ++t) {
            if (((int*)(smf + FLGO))[t]) continue;
            int ii1 = ((int*)(smf + I1O))[t], ii2 = ((int*)(smf + I2O))[t];
            bool in1 = (ii1 == e), in2 = (ii2 == e);
            if (in1) imp += smf[W1O + t];
            if (in2) imp += smf[W2O + t];
            float kth = (in1 || in2) ? smf[V3O + t] : smf[V2O + t];
            float sd  = smf[LOGI + t * LSTR + NEXP + e];
            float lg  = smf[LOGI + t * LSTR + e];
            float z   = (lg - kth) / (sd + EPS);
            ld += 0.5f * (1.f + erff(z * 0.70710678118654752f));
        }
        smf[IMPO + g * 64 + e] = imp;
        smf[LDO  + g * 64 + e] = ld;
    }
    __syncthreads();

    // ---- fused fixup: warp-per-flagged-token, candidate-only exact dots ----
    const int nflag = ((int*)(smf + NFLG))[0];
    for (int idx = wid; idx < nflag; idx += 8) {
        const int t  = ((int*)(smf + LIST))[idx];
        const int tg = tok0 + t;
        float lga[2], sda[2], nza[2];
#pragma unroll
        for (int j = 0; j < 2; ++j) {
            int e = lane + 32 * j;
            lga[j] = smf[LOGI + t * LSTR + e];
            sda[j] = smf[LOGI + t * LSTR + NEXP + e];
            nza[j] = fmaf(noise[(size_t)tg * NEXP + e], sda[j], lga[j]);
        }
        // approx 3rd max via 3 argmax-exclude passes
        float c0 = nza[0], c1 = nza[1];
        float v3a = -CUDART_INF_F;
#pragma unroll
        for (int pass = 0; pass < 3; ++pass) {
            float m  = fmaxf(c0, c1);
            int  mid = (c0 >= c1) ? (lane * 2) : (lane * 2 + 1);
#pragma unroll
            for (int o = 16; o > 0; o >>= 1) {
                float mv = __shfl_xor_sync(0xFFFFFFFFu, m, o);
                int   mi = __shfl_xor_sync(0xFFFFFFFFu, mid, o);
                if (mv > m || (mv == m && mi < mid)) { m = mv; mid = mi; }
            }
            v3a = m;
            if (mid == lane * 2)     c0 = -CUDART_INF_F;
            if (mid == lane * 2 + 1) c1 = -CUDART_INF_F;
        }
        const float thr = v3a - WINDOW;
        unsigned mask0 = __ballot_sync(0xFFFFFFFFu, nza[0] >= thr);
        unsigned mask1 = __ballot_sync(0xFFFFFFFFu, nza[1] >= thr);

        const float* xr = x + (size_t)tg * DIM;
        float v1x = -CUDART_INF_F, v2x = -CUDART_INF_F, v3x = -CUDART_INF_F;
        int i1 = 0, i2 = 0;

#pragma unroll 1
        for (int half = 0; half < 2; ++half) {
            unsigned m = half ? mask1 : mask0;
            while (m) {
                int e = __ffs(m) - 1 + half * 32;
                m &= m - 1;
                const float* wg = Wg + (size_t)e * DIM;
                const float* wnp = Wn + (size_t)e * DIM;
                float sg = 0.f, sn = 0.f;
#pragma unroll
                for (int jj = 0; jj < 16; ++jj) {
                    int k = lane * 4 + jj * 128;
                    float4 xv = *(const float4*)(xr + k);
                    float4 g4 = *(const float4*)(wg + k);
                    float4 n4 = *(const float4*)(wnp + k);
                    sg = fmaf(xv.x, g4.x, fmaf(xv.y, g4.y, fmaf(xv.z, g4.z, fmaf(xv.w, g4.w, sg))));
                    sn = fmaf(xv.x, n4.x, fmaf(xv.y, n4.y, fmaf(xv.z, n4.z, fmaf(xv.w, n4.w, sn))));
                }
#pragma unroll
                for (int o = 16; o > 0; o >>= 1) {
                    sg += __shfl_xor_sync(0xFFFFFFFFu, sg, o);
                    sn += __shfl_xor_sync(0xFFFFFFFFu, sn, o);
                }
                float sp  = fmaxf(sn, 0.f) + log1pf(expf(-fabsf(sn)));
                float sdx = sp + EPS;
                float nzx = fmaf(noise[(size_t)tg * NEXP + e], sdx, sg);
                if (nzx > v1x)      { v3x = v2x; v2x = v1x; i2 = i1; v1x = nzx; i1 = e; }
                else if (nzx > v2x) { v3x = v2x; v2x = nzx; i2 = e; }
                else if (nzx > v3x) { v3x = nzx; }
            }
        }

        float ed  = expf(v2x - v1x);
        float inv = 1.f / (1.f + ed);
        float w1 = inv, w2 = ed * inv;
        if (lane == 0) {
            out[2 * tg]                    = (float)i1;
            out[2 * tg + 1]                = (float)i2;
            out[2 * N_TOKENS + 2 * tg]     = w1;
            out[2 * N_TOKENS + 2 * tg + 1] = w2;
            out[4 * N_TOKENS + tg]         = w1;
            smf[FIMP + wid * 64 + i1] += w1;
            smf[FIMP + wid * 64 + i2] += w2;
        }
#pragma unroll
        for (int j = 0; j < 2; ++j) {
            int e = lane + 32 * j;
            float kth = (e == i1 || e == i2) ? v3x : v2x;
            float z = (lga[j] - kth) / (sda[j] + EPS);
            smf[FLD2 + wid * 64 + e] += 0.5f * (1.f + erff(z * 0.70710678118654752f));
        }
    }
    __syncthreads();

    // per-block partial store (approx + fixup)
    if (tid < NEXP) {
        float si = 0.f, sl = 0.f;
#pragma unroll
        for (int g = 0; g < 4; ++g) { si += smf[IMPO + g * 64 + tid]; sl += smf[LDO + g * 64 + tid]; }
#pragma unroll
        for (int q = 0; q < 8; ++q) { si += smf[FIMP + q * 64 + tid]; sl += smf[FLD2 + q * 64 + tid]; }
        g_imp_part [b * NEXP + tid] = si;
        g_load_part[b * NEXP + tid] = sl;
    }

    // ---- fused finalize: last block computes aux ----
    __threadfence();
    __shared__ int lastflag;
    if (tid == 0) {
        unsigned tk = atomicAdd(&g_ticket, 1u);
        lastflag = (tk == (unsigned)(NBLK - 1));
    }
    __syncthreads();
    if (!lastflag) return;

    __shared__ float fimp[4][64], fld[4][64];
    {
        const int e = tid & 63, g = tid >> 6;   // 4 groups
        float si = 0.f, sl = 0.f;
        for (int q = g; q < NBLK; q += 4) {
            si += g_imp_part [q * NEXP + e];
            sl += g_load_part[q * NEXP + e];
        }
        fimp[g][e] = si; fld[g][e] = sl;
    }
    __syncthreads();
    __shared__ float timp[64], tld[64];
    if (tid < 64) {
        timp[tid] = fimp[0][tid] + fimp[1][tid] + fimp[2][tid] + fimp[3][tid];
        tld[tid]  = fld[0][tid]  + fld[1][tid]  + fld[2][tid]  + fld[3][tid];
    }
    __syncthreads();
    if (tid < 32) {
        float si = timp[tid] + timp[tid + 32];
        float sl = tld[tid]  + tld[tid + 32];
#pragma unroll
        for (int o = 16; o > 0; o >>= 1) {
            si += __shfl_xor_sync(0xFFFFFFFFu, si, o);
            sl += __shfl_xor_sync(0xFFFFFFFFu, sl, o);
        }
        float mi = si * (1.f / NEXP), ml = sl * (1.f / NEXP);
        float d0 = timp[tid] - mi, d1 = timp[tid + 32] - mi;
        float e0 = tld[tid]  - ml, e1 = tld[tid + 32]  - ml;
        float vi = d0 * d0 + d1 * d1;
        float vl = e0 * e0 + e1 * e1;
#pragma unroll
        for (int o = 16; o > 0; o >>= 1) {
            vi += __shfl_xor_sync(0xFFFFFFFFu, vi, o);
            vl += __shfl_xor_sync(0xFFFFFFFFu, vl, o);
        }
        vi *= (1.f / NEXP); vl *= (1.f / NEXP);
        if (tid == 0)
            out[5 * N_TOKENS] = 0.1f * (vi / (mi * mi + EPS)) + 0.1f * (vl / (ml * ml + EPS));
    }
}

extern "C" void kernel_launch(void* const* d_in, const int* in_sizes, int n_in,
                              void* d_out, int out_size)
{
    const float* x     = (const float*)d_in[0];
    const float* noise = (const float*)d_in[1];
    const float* Wg    = (const float*)d_in[2];
    const float* Wn    = (const float*)d_in[3];
    float* out = (float*)d_out;

    cudaFuncSetAttribute(router_main_kernel,
                         cudaFuncAttributeMaxDynamicSharedMemorySize, SMEM_BYTES);
    wpack_kernel<<<128, 256>>>(Wg, Wn);
    router_main_kernel<<<NBLK, NTHREADS, SMEM_BYTES>>>(x, noise, Wg, Wn, out);
}